// round 4
// baseline (speedup 1.0000x reference)
#include <cuda_runtime.h>
#include <cuda_bf16.h>
#include <math_constants.h>

// ParatopeAwareReadout: single-pass segmented online-softmax weighted readout.
// batch is sorted -> each segment b occupies a contiguous index range.
// One block per segment, 256 threads (8 warps). Each warp streams full
// 256-float rows of h (2x float4 per lane), computes the attention logit via
// butterfly warp-reduce, and maintains an online softmax state
// (m, d, num[256] spread 8 floats/lane). Two interleaved node streams per warp
// provide MLP and hide the shuffle/exp dependency chain.

#define DIMC  256
#define BETA_C  1.0f
#define GAMMA_C 0.5f

// 1 if the node_mask buffer is int32-typed, 0 if it is 1-byte bool.
__device__ int g_mask_is_i32;

// Sniff the mask dtype from its byte pattern. For a 1-byte bool array of
// random 0/1, ~50% of bytes at offsets i%4 != 0 are nonzero. For an int32
// array of 0/1 values (little-endian), ALL bytes at offsets i%4 != 0 within
// the first N bytes are zero. Deterministic, allocation-free.
__global__ void mask_dtype_sniff_kernel(const unsigned char* __restrict__ m, int nbytes)
{
    __shared__ int s_cnt;
    if (threadIdx.x == 0) s_cnt = 0;
    __syncthreads();
    int local = 0;
    for (int i = threadIdx.x; i < nbytes; i += blockDim.x)
        if ((i & 3) != 0 && m[i] != 0) local++;
    #pragma unroll
    for (int o = 16; o > 0; o >>= 1)
        local += __shfl_xor_sync(0xffffffffu, local, o);
    if ((threadIdx.x & 31) == 0) atomicAdd(&s_cnt, local);
    __syncthreads();
    if (threadIdx.x == 0) g_mask_is_i32 = (s_cnt == 0) ? 1 : 0;
}

__device__ __forceinline__ void online_update(
    float logit, bool msk,
    const float4& ha, const float4& hb,
    float& m, float& d, float4& na, float4& nb)
{
    if (!msk) return;                // mask is uniform across the warp (per node)
    float mn = fmaxf(m, logit);
    float sc = __expf(m - mn);       // m == -inf first time -> exp(-inf) = 0
    float c  = __expf(logit - mn);
    d = d * sc + c;
    na.x = fmaf(na.x, sc, c * ha.x);
    na.y = fmaf(na.y, sc, c * ha.y);
    na.z = fmaf(na.z, sc, c * ha.z);
    na.w = fmaf(na.w, sc, c * ha.w);
    nb.x = fmaf(nb.x, sc, c * hb.x);
    nb.y = fmaf(nb.y, sc, c * hb.y);
    nb.z = fmaf(nb.z, sc, c * hb.z);
    nb.w = fmaf(nb.w, sc, c * hb.w);
    m = mn;
}

__global__ void __launch_bounds__(256, 3)
paratope_readout_kernel(const float* __restrict__ h,
                        const int* __restrict__ batch,
                        const unsigned char* __restrict__ mask,
                        const float* __restrict__ pp,
                        const float* __restrict__ sp,
                        const float* __restrict__ q,
                        float* __restrict__ out,
                        int N)
{
    __shared__ float s_num[8][DIMC];
    __shared__ float s_m[8];
    __shared__ float s_d[8];
    __shared__ int   s_range[2];

    const int b    = blockIdx.x;
    const int tid  = threadIdx.x;
    const int w    = tid >> 5;
    const int lane = tid & 31;

    const int mask_i32 = g_mask_is_i32;
    const int* mask32  = (const int*)mask;

    // Segment bounds via binary search on sorted batch (2 threads; the
    // __syncthreads below overlaps the q vector loads issued by all threads).
    if (tid < 2) {
        int key = b + tid;           // tid 0 -> lower bound of b, tid 1 -> lower bound of b+1
        int lo = 0, hi = N;
        while (lo < hi) { int mid = (lo + hi) >> 1; if (batch[mid] < key) lo = mid + 1; else hi = mid; }
        s_range[tid] = lo;
    }

    // q in registers: lane holds dims [4*lane,4*lane+4) and [128+4*lane, ...)
    const float4 q0 = *reinterpret_cast<const float4*>(q + 4 * lane);
    const float4 q1 = *reinterpret_cast<const float4*>(q + 128 + 4 * lane);

    __syncthreads();
    const int start = s_range[0];
    const int end   = s_range[1];

    // Two independent online-softmax streams per warp.
    float  m0 = -CUDART_INF_F, d0 = 0.f;
    float4 n00 = {0.f,0.f,0.f,0.f}, n01 = {0.f,0.f,0.f,0.f};
    float  m1 = -CUDART_INF_F, d1 = 0.f;
    float4 n10 = {0.f,0.f,0.f,0.f}, n11 = {0.f,0.f,0.f,0.f};

    int i = start + w;
    // Main loop: process nodes i (stream 0) and i+8 (stream 1) together.
    for (; i + 8 < end; i += 16) {
        // Issue scalar side-input loads first so they join the front LDG batch.
        float pa = pp[i],   sa = sp[i];
        float pb = pp[i+8], sb = sp[i+8];
        bool ma = mask_i32 ? (mask32[i]   != 0) : (mask[i]   != 0);
        bool mb = mask_i32 ? (mask32[i+8] != 0) : (mask[i+8] != 0);

        const float* ra = h + (size_t)i * DIMC;
        const float* rb = h + (size_t)(i + 8) * DIMC;
        float4 ha0 = *reinterpret_cast<const float4*>(ra + 4 * lane);
        float4 ha1 = *reinterpret_cast<const float4*>(ra + 128 + 4 * lane);
        float4 hb0 = *reinterpret_cast<const float4*>(rb + 4 * lane);
        float4 hb1 = *reinterpret_cast<const float4*>(rb + 128 + 4 * lane);

        float da = ha0.x*q0.x + ha0.y*q0.y + ha0.z*q0.z + ha0.w*q0.w
                 + ha1.x*q1.x + ha1.y*q1.y + ha1.z*q1.z + ha1.w*q1.w;
        float db = hb0.x*q0.x + hb0.y*q0.y + hb0.z*q0.z + hb0.w*q0.w
                 + hb1.x*q1.x + hb1.y*q1.y + hb1.z*q1.z + hb1.w*q1.w;
        #pragma unroll
        for (int o = 16; o > 0; o >>= 1) {
            da += __shfl_xor_sync(0xffffffffu, da, o);
            db += __shfl_xor_sync(0xffffffffu, db, o);
        }
        float la = da + BETA_C * pa + GAMMA_C * sa;
        float lb = db + BETA_C * pb + GAMMA_C * sb;

        online_update(la, ma, ha0, ha1, m0, d0, n00, n01);
        online_update(lb, mb, hb0, hb1, m1, d1, n10, n11);
    }
    // Tail node (at most one per warp).
    if (i < end) {
        float pa = pp[i], sa = sp[i];
        bool ma = mask_i32 ? (mask32[i] != 0) : (mask[i] != 0);
        const float* ra = h + (size_t)i * DIMC;
        float4 ha0 = *reinterpret_cast<const float4*>(ra + 4 * lane);
        float4 ha1 = *reinterpret_cast<const float4*>(ra + 128 + 4 * lane);
        float da = ha0.x*q0.x + ha0.y*q0.y + ha0.z*q0.z + ha0.w*q0.w
                 + ha1.x*q1.x + ha1.y*q1.y + ha1.z*q1.z + ha1.w*q1.w;
        #pragma unroll
        for (int o = 16; o > 0; o >>= 1)
            da += __shfl_xor_sync(0xffffffffu, da, o);
        float la = da + BETA_C * pa + GAMMA_C * sa;
        online_update(la, ma, ha0, ha1, m0, d0, n00, n01);
    }

    // Merge the two streams of this warp.
    float Mw = fmaxf(m0, m1);
    float sc0 = (d0 > 0.f) ? __expf(m0 - Mw) : 0.f;
    float sc1 = (d1 > 0.f) ? __expf(m1 - Mw) : 0.f;
    float dw = d0 * sc0 + d1 * sc1;
    float4 nw0, nw1;
    nw0.x = n00.x*sc0 + n10.x*sc1;  nw0.y = n00.y*sc0 + n10.y*sc1;
    nw0.z = n00.z*sc0 + n10.z*sc1;  nw0.w = n00.w*sc0 + n10.w*sc1;
    nw1.x = n01.x*sc0 + n11.x*sc1;  nw1.y = n01.y*sc0 + n11.y*sc1;
    nw1.z = n01.z*sc0 + n11.z*sc1;  nw1.w = n01.w*sc0 + n11.w*sc1;

    // Publish warp state to smem.
    if (lane == 0) { s_m[w] = Mw; s_d[w] = dw; }
    *reinterpret_cast<float4*>(&s_num[w][4 * lane])       = nw0;
    *reinterpret_cast<float4*>(&s_num[w][128 + 4 * lane]) = nw1;
    __syncthreads();

    // Cross-warp merge: thread tid owns output dim tid.
    float Mg = s_m[0];
    #pragma unroll
    for (int ww = 1; ww < 8; ww++) Mg = fmaxf(Mg, s_m[ww]);

    float D = 0.f, acc = 0.f;
    #pragma unroll
    for (int ww = 0; ww < 8; ww++) {
        float dwv = s_d[ww];
        float scw = (dwv > 0.f) ? __expf(s_m[ww] - Mg) : 0.f;
        D   += dwv * scw;
        acc  = fmaf(s_num[ww][tid], scw, acc);
    }
    out[(size_t)b * DIMC + tid] = (D > 0.f) ? (acc / D) : 0.f;
}

extern "C" void kernel_launch(void* const* d_in, const int* in_sizes, int n_in,
                              void* d_out, int out_size)
{
    const float*         h    = (const float*)d_in[0];
    const int*           bat  = (const int*)d_in[1];
    const unsigned char* msk  = (const unsigned char*)d_in[2];
    const float*         pp   = (const float*)d_in[3];
    const float*         sp   = (const float*)d_in[4];
    const float*         q    = (const float*)d_in[5];
    float*               out  = (float*)d_out;
    const int N = in_sizes[1];
    const int B = out_size / DIMC;

    int sniff = N < 4096 ? N : 4096;
    mask_dtype_sniff_kernel<<<1, 256>>>(msk, sniff);
    paratope_readout_kernel<<<B, 256>>>(h, bat, msk, pp, sp, q, out, N);
}

// round 15
// speedup vs baseline: 1.5052x; 1.5052x over previous
#include <cuda_runtime.h>
#include <cuda_bf16.h>
#include <math_constants.h>

// ParatopeAwareReadout: single-pass segmented online-softmax weighted readout.
// batch is sorted -> each segment b occupies a contiguous index range.
// One block per segment, 256 threads (8 warps), 4 blocks/SM (32 warps/SM).
// Each warp streams one node per iteration (full 256-float row, 2x float4 per
// lane) with an explicit one-iteration-ahead double-buffer prefetch so the
// LDG.128s for node i+8 are in flight while node i is processed. Online
// softmax state (m, d, acc[256] spread 8 floats/lane) per warp; cross-warp
// merge in smem.

#define DIMC  256
#define BETA_C  1.0f
#define GAMMA_C 0.5f

// 1 if the node_mask buffer is int32-typed, 0 if it is 1-byte bool.
__device__ int g_mask_is_i32;

// Sniff the mask dtype from its byte pattern (see round 2 notes): for int32
// 0/1 data every byte at offset i%4!=0 is zero; for 1-byte bools ~50% are not.
__global__ void mask_dtype_sniff_kernel(const unsigned char* __restrict__ m, int nbytes)
{
    __shared__ int s_cnt;
    if (threadIdx.x == 0) s_cnt = 0;
    __syncthreads();
    int local = 0;
    for (int i = threadIdx.x; i < nbytes; i += blockDim.x)
        if ((i & 3) != 0 && m[i] != 0) local++;
    #pragma unroll
    for (int o = 16; o > 0; o >>= 1)
        local += __shfl_xor_sync(0xffffffffu, local, o);
    if ((threadIdx.x & 31) == 0) atomicAdd(&s_cnt, local);
    __syncthreads();
    if (threadIdx.x == 0) g_mask_is_i32 = (s_cnt == 0) ? 1 : 0;
}

__global__ void __launch_bounds__(256, 4)
paratope_readout_kernel(const float* __restrict__ h,
                        const int* __restrict__ batch,
                        const unsigned char* __restrict__ mask,
                        const float* __restrict__ pp,
                        const float* __restrict__ sp,
                        const float* __restrict__ q,
                        float* __restrict__ out,
                        int N)
{
    __shared__ float s_num[8][DIMC];
    __shared__ float s_m[8];
    __shared__ float s_d[8];
    __shared__ int   s_range[2];

    const int b    = blockIdx.x;
    const int tid  = threadIdx.x;
    const int w    = tid >> 5;
    const int lane = tid & 31;

    const int  mask_i32 = g_mask_is_i32;
    const int* mask32   = (const int*)mask;

    // Segment bounds via binary search on sorted batch; the __syncthreads
    // below overlaps with the q loads issued by all threads.
    if (tid < 2) {
        int key = b + tid;
        int lo = 0, hi = N;
        while (lo < hi) { int mid = (lo + hi) >> 1; if (batch[mid] < key) lo = mid + 1; else hi = mid; }
        s_range[tid] = lo;
    }

    // q in registers: lane holds dims [4*lane,4*lane+4) and [128+4*lane, ...)
    const float4 q0 = *reinterpret_cast<const float4*>(q + 4 * lane);
    const float4 q1 = *reinterpret_cast<const float4*>(q + 128 + 4 * lane);

    __syncthreads();
    const int start = s_range[0];
    const int end   = s_range[1];

    // Online softmax state for this warp.
    float  m = -CUDART_INF_F, d = 0.f;
    float4 a0 = {0.f,0.f,0.f,0.f}, a1 = {0.f,0.f,0.f,0.f};

    // Prime the pipeline: load node start+w.
    int i = start + w;
    float4 c0, c1;
    float  side = 0.f;
    bool   mk   = false;
    if (i < end) {
        const float* r = h + (size_t)i * DIMC;
        c0   = __ldcs(reinterpret_cast<const float4*>(r + 4 * lane));
        c1   = __ldcs(reinterpret_cast<const float4*>(r + 128 + 4 * lane));
        side = BETA_C * __ldg(pp + i) + GAMMA_C * __ldg(sp + i);
        mk   = mask_i32 ? (mask32[i] != 0) : (mask[i] != 0);
    }

    for (; i < end; i += 8) {
        // ---- prefetch node i+8 (clamped address keeps this branch-free) ----
        const int  nx = i + 8;
        const bool hn = nx < end;
        const int  ax = hn ? nx : i;
        const float* rn = h + (size_t)ax * DIMC;
        float4 p0 = __ldcs(reinterpret_cast<const float4*>(rn + 4 * lane));
        float4 p1 = __ldcs(reinterpret_cast<const float4*>(rn + 128 + 4 * lane));
        float  pside = BETA_C * __ldg(pp + ax) + GAMMA_C * __ldg(sp + ax);
        bool   pmk   = mask_i32 ? (mask32[ax] != 0) : (mask[ax] != 0);

        // ---- process current node (loads for it completed last iteration) ----
        float dt = c0.x*q0.x + c0.y*q0.y + c0.z*q0.z + c0.w*q0.w
                 + c1.x*q1.x + c1.y*q1.y + c1.z*q1.z + c1.w*q1.w;
        #pragma unroll
        for (int o = 16; o > 0; o >>= 1)
            dt += __shfl_xor_sync(0xffffffffu, dt, o);
        float lg = dt + side;

        if (mk) {                       // mask is uniform across the warp
            float mn = fmaxf(m, lg);
            float sc = __expf(m - mn);  // m == -inf first time -> 0
            float c  = __expf(lg - mn);
            d = d * sc + c;
            a0.x = fmaf(a0.x, sc, c * c0.x);
            a0.y = fmaf(a0.y, sc, c * c0.y);
            a0.z = fmaf(a0.z, sc, c * c0.z);
            a0.w = fmaf(a0.w, sc, c * c0.w);
            a1.x = fmaf(a1.x, sc, c * c1.x);
            a1.y = fmaf(a1.y, sc, c * c1.y);
            a1.z = fmaf(a1.z, sc, c * c1.z);
            a1.w = fmaf(a1.w, sc, c * c1.w);
            m = mn;
        }

        // ---- rotate buffers ----
        c0 = p0; c1 = p1; side = pside; mk = hn && pmk;
    }

    // Publish warp state to smem.
    if (lane == 0) { s_m[w] = m; s_d[w] = d; }
    *reinterpret_cast<float4*>(&s_num[w][4 * lane])       = a0;
    *reinterpret_cast<float4*>(&s_num[w][128 + 4 * lane]) = a1;
    __syncthreads();

    // Cross-warp merge: thread tid owns output dim tid.
    float Mg = s_m[0];
    #pragma unroll
    for (int ww = 1; ww < 8; ww++) Mg = fmaxf(Mg, s_m[ww]);

    float D = 0.f, acc = 0.f;
    #pragma unroll
    for (int ww = 0; ww < 8; ww++) {
        float dwv = s_d[ww];
        float scw = (dwv > 0.f) ? __expf(s_m[ww] - Mg) : 0.f;
        D   += dwv * scw;
        acc  = fmaf(s_num[ww][tid], scw, acc);
    }
    out[(size_t)b * DIMC + tid] = (D > 0.f) ? (acc / D) : 0.f;
}

extern "C" void kernel_launch(void* const* d_in, const int* in_sizes, int n_in,
                              void* d_out, int out_size)
{
    const float*         h    = (const float*)d_in[0];
    const int*           bat  = (const int*)d_in[1];
    const unsigned char* msk  = (const unsigned char*)d_in[2];
    const float*         pp   = (const float*)d_in[3];
    const float*         sp   = (const float*)d_in[4];
    const float*         q    = (const float*)d_in[5];
    float*               out  = (float*)d_out;
    const int N = in_sizes[1];
    const int B = out_size / DIMC;

    int sniff = N < 4096 ? N : 4096;
    mask_dtype_sniff_kernel<<<1, 256>>>(msk, sniff);
    paratope_readout_kernel<<<B, 256>>>(h, bat, msk, pp, sp, q, out, N);
}